// round 13
// baseline (speedup 1.0000x reference)
#include <cuda_runtime.h>
#include <cstdint>

// ---------------------------------------------------------------------------
// CML2DWithStats, cluster halo-exchange kernel (Round 13).
//
// R7/R8/R9/R12 falsified every intra-decomposition tweak of the temporal-
// blocking design (R6, 197us): the binding cost is the cone's redundant halo
// work itself. This kernel removes it: one 8-CTA cluster per (batch,chan)
// plane; CTA rank owns image rows [32*rank, 32*rank+31]. Per step each CTA
// computes ONLY its 32 rows; the single boundary row needed from each
// neighbor is pushed via st.shared::cluster (DSMEM) into the neighbor's dst
// halo slot, and one barrier.cluster per step orders everything.
//
// smem/buffer: 34 physical rows (halo top=0, interior 1..32, halo bot=33)
// x 264 cols, double buffered (70 KB). Rank-0 top / rank-7 bottom halos are
// never written after the initial zeroing -> exact conv zero padding.
// Drive and weights are fully register-resident (cluster.sync flushes L1).
// ---------------------------------------------------------------------------

#define SSTR  264                      // smem row stride (floats)
#define PROWS 34                       // physical rows per buffer
#define NBUF  (PROWS * SSTR)           // 8976 floats per buffer
#define PL    8388608L                 // elements per output plane

__device__ __forceinline__ uint32_t mapa32(uint32_t a, uint32_t rank) {
    uint32_t d;
    asm("mapa.shared::cluster.u32 %0, %1, %2;" : "=r"(d) : "r"(a), "r"(rank));
    return d;
}
__device__ __forceinline__ void stc4(uint32_t addr, float4 v) {
    asm volatile("st.shared::cluster.v4.f32 [%0], {%1, %2, %3, %4};"
                 :: "r"(addr), "f"(v.x), "f"(v.y), "f"(v.z), "f"(v.w) : "memory");
}
#define CLUSTER_SYNC() do { \
    asm volatile("barrier.cluster.arrive.aligned;" ::: "memory"); \
    asm volatile("barrier.cluster.wait.aligned;"   ::: "memory"); \
} while (0)

// mapped[x0-1 .. x0+4]: one LDS.128 + 2 shuffles; edge lanes scalar-LDS the
// in-row pad/neighbor columns (4-col zero pads exist both sides).
__device__ __forceinline__ void load6(const float* __restrict__ p, int lane, float m[6]) {
    float4 v = *reinterpret_cast<const float4*>(p);
    float left  = __shfl_up_sync(0xffffffffu, v.w, 1);
    float right = __shfl_down_sync(0xffffffffu, v.x, 1);
    if (lane == 0)  left  = p[-1];
    if (lane == 31) right = p[4];
    m[0] = left; m[1] = v.x; m[2] = v.y; m[3] = v.z; m[4] = v.w; m[5] = right;
}

// Folded update: g = sum(W .* mapped_nbr) + 0.15*drive, clamped.
__device__ __forceinline__ void taps(const float* __restrict__ W,
                                     const float A[6], const float B[6],
                                     const float C[6], const float dd[4],
                                     float g[4]) {
    #pragma unroll
    for (int j = 0; j < 4; ++j) {
        float t =      W[0] * A[j];
        t = fmaf(W[1], A[j + 1], t);
        t = fmaf(W[2], A[j + 2], t);
        t = fmaf(W[3], B[j],     t);
        t = fmaf(W[4], B[j + 1], t);
        t = fmaf(W[5], B[j + 2], t);
        t = fmaf(W[6], C[j],     t);
        t = fmaf(W[7], C[j + 1], t);
        t = fmaf(W[8], C[j + 2], t);
        t = fmaf(0.15f, dd[j],   t);
        g[j] = fminf(fmaxf(t, 1e-4f), 1.0f - 1e-4f);
    }
}

__device__ __forceinline__ float4 lmap(const float g[4]) {
    float4 m;
    m.x = (3.9f * g[0]) * (1.0f - g[0]);
    m.y = (3.9f * g[1]) * (1.0f - g[1]);
    m.z = (3.9f * g[2]) * (1.0f - g[2]);
    m.w = (3.9f * g[3]) * (1.0f - g[3]);
    return m;
}

// One step for this thread's 4 rows (physical R0..R0+3, R0 = 1+4*ty).
// All rows unconditional. Boundary warps push their boundary row into the
// neighbor's dst halo slot via DSMEM.
template<bool LAST>
__device__ __forceinline__ void step_rows(
    const float* __restrict__ src, float* __restrict__ dst, uint32_t dst_u32,
    int ty, int lane, int x0, uint32_t rank,
    const float (&ddreg)[4][4], const float* __restrict__ W,
    float (&sum)[4][4], float (&sq)[4][4],
    float* __restrict__ outBase)
{
    const int R0 = 1 + 4 * ty;
    const float* pA = src + (R0 - 1) * SSTR + 4 + x0;
    float A[6], B[6], C[6];
    load6(pA,        lane, A);
    load6(pA + SSTR, lane, B);
    #pragma unroll
    for (int i = 0; i < 4; ++i) {
        load6(pA + (i + 2) * SSTR, lane, C);
        float g[4];
        taps(W, A, B, C, ddreg[i], g);
        #pragma unroll
        for (int j = 0; j < 4; ++j) {
            sum[i][j] += g[j];
            sq[i][j]   = fmaf(g[j], g[j], sq[i][j]);
        }
        if (!LAST) {
            const float4 mv = lmap(g);
            *reinterpret_cast<float4*>(dst + (R0 + i) * SSTR + 4 + x0) = mv;
            // push boundary rows into neighbors' dst halo slots
            if (ty == 0 && i == 0 && rank > 0) {
                uint32_t ra = mapa32(dst_u32 + (uint32_t)(33 * SSTR + 4 + x0) * 4u,
                                     rank - 1);
                stc4(ra, mv);                    // my row 0 -> neighbor's bottom halo
            }
            if (ty == 7 && i == 3 && rank < 7) {
                uint32_t ra = mapa32(dst_u32 + (uint32_t)(0 * SSTR + 4 + x0) * 4u,
                                     rank + 1);
                stc4(ra, mv);                    // my row 31 -> neighbor's top halo
            }
        } else {
            const int y = 32 * (int)rank + 4 * ty + i;
            const long o = (long)y * 256 + x0;
            *reinterpret_cast<float4*>(outBase + o) =
                make_float4(g[0], g[1], g[2], g[3]);
            const float4 dl = make_float4(g[0] - ddreg[i][0], g[1] - ddreg[i][1],
                                          g[2] - ddreg[i][2], g[3] - ddreg[i][3]);
            *reinterpret_cast<float4*>(outBase + 3L * PL + o) = dl;
            *reinterpret_cast<float4*>(outBase + 4L * PL + o) = dl;
        }
        #pragma unroll
        for (int q = 0; q < 6; ++q) { A[q] = B[q]; B[q] = C[q]; }
    }
}

__global__ void __launch_bounds__(512, 1) __cluster_dims__(8, 1, 1)
cml_cluster_kernel(const float* __restrict__ drive,
                   const float* __restrict__ Kl,
                   float* __restrict__ out)
{
    extern __shared__ float smem[];
    float* b0 = smem;
    float* b1 = smem + NBUF;

    uint32_t smem_u32;
    asm("{ .reg .u64 t; cvta.to.shared.u64 t, %1; cvt.u32.u64 %0, t; }"
        : "=r"(smem_u32) : "l"(smem));
    const uint32_t b0_u32 = smem_u32;
    const uint32_t b1_u32 = smem_u32 + NBUF * 4u;

    const int bc     = blockIdx.x >> 3;       // plane (b*8 + c)
    const uint32_t rank = blockIdx.x & 7;     // == cluster_ctarank (dims (8,1,1))
    const int ch     = bc & 7;
    const float* dpl     = drive + (long)bc * 65536L;
    float*       outBase = out   + (long)bc * 65536L;

    const int tid  = threadIdx.x;
    const int tx   = tid & 63;                // x group (4 columns)
    const int ty   = tid >> 6;                // 0..7, warp-uniform
    const int lane = tid & 31;
    const int x0   = tx << 2;

    // Folded conv weights: W = 0.255*K, +0.595 at center.
    float W[9];
    #pragma unroll
    for (int i = 0; i < 9; ++i) W[i] = 0.255f * __ldg(&Kl[ch * 9 + i]);
    W[4] += 0.595f;

    // Drive for this thread's 4 rows: register-resident for all 15 steps.
    float ddreg[4][4];
    #pragma unroll
    for (int i = 0; i < 4; ++i) {
        const int y = 32 * (int)rank + 4 * ty + i;
        const float4 d4 = *reinterpret_cast<const float4*>(dpl + y * 256 + x0);
        ddreg[i][0] = d4.x; ddreg[i][1] = d4.y;
        ddreg[i][2] = d4.z; ddreg[i][3] = d4.w;
    }

    // Zero both buffers: x-pads + edge-cluster halo rows stay 0 forever
    // (= conv zero padding).
    for (int i = tid; i < 2 * NBUF; i += 512) smem[i] = 0.0f;
    __syncthreads();

    // Init b0: mapped(drive) for physical rows 0..33 (y = 32*rank + p - 1);
    // out-of-image rows (rank-0 top / rank-7 bottom halo) stay zero.
    for (int idx = tid; idx < PROWS * 64; idx += 512) {
        const int p  = idx >> 6;
        const int xg = (idx & 63) << 2;
        const int y  = 32 * (int)rank + p - 1;
        if (y >= 0 && y < 256) {
            const float4 d = *reinterpret_cast<const float4*>(dpl + y * 256 + xg);
            float4 m;
            m.x = (3.9f * d.x) * (1.0f - d.x);
            m.y = (3.9f * d.y) * (1.0f - d.y);
            m.z = (3.9f * d.z) * (1.0f - d.z);
            m.w = (3.9f * d.w) * (1.0f - d.w);
            *reinterpret_cast<float4*>(b0 + p * SSTR + 4 + xg) = m;
        }
    }
    // Cluster-wide: everyone's init (incl. zeroing of b1 halo slots) must be
    // done before any step-1 DSMEM send can land in a peer's b1.
    CLUSTER_SYNC();

    float sum[4][4], sq[4][4];
    #pragma unroll
    for (int i = 0; i < 4; ++i)
        #pragma unroll
        for (int j = 0; j < 4; ++j) { sum[i][j] = 0.0f; sq[i][j] = 0.0f; }

    const float* src = b0;
    float*       dst = b1;
    uint32_t     dst_u32 = b1_u32;
    for (int s = 1; s <= 14; ++s) {
        step_rows<false>(src, dst, dst_u32, ty, lane, x0, rank,
                         ddreg, W, sum, sq, outBase);
        CLUSTER_SYNC();                        // orders dst writes + DSMEM sends
        const float* t = src; src = dst; dst = const_cast<float*>(t);
        dst_u32 = (dst_u32 == b1_u32) ? b0_u32 : b1_u32;
    }
    // Step 15: outputs only, no sends.
    step_rows<true>(src, dst, dst_u32, ty, lane, x0, rank,
                    ddreg, W, sum, sq, outBase);

    // mean / var from register accumulators.
    const float inv15 = 1.0f / 15.0f;
    #pragma unroll
    for (int i = 0; i < 4; ++i) {
        const int y = 32 * (int)rank + 4 * ty + i;
        const long o = (long)y * 256 + x0;
        float4 mn, vr;
        mn.x = sum[i][0] * inv15;
        mn.y = sum[i][1] * inv15;
        mn.z = sum[i][2] * inv15;
        mn.w = sum[i][3] * inv15;
        vr.x = fmaf(-mn.x, mn.x, sq[i][0] * inv15);
        vr.y = fmaf(-mn.y, mn.y, sq[i][1] * inv15);
        vr.z = fmaf(-mn.z, mn.z, sq[i][2] * inv15);
        vr.w = fmaf(-mn.w, mn.w, sq[i][3] * inv15);
        *reinterpret_cast<float4*>(outBase + 1L * PL + o) = mn;
        *reinterpret_cast<float4*>(outBase + 2L * PL + o) = vr;
    }

    // No CTA may exit while a peer could still target its smem (none do after
    // the last sync, but keep exit ordering well-defined).
    CLUSTER_SYNC();
}

extern "C" void kernel_launch(void* const* d_in, const int* in_sizes, int n_in,
                              void* d_out, int out_size)
{
    const float* drive = (const float*)d_in[0];
    const float* Kl    = (const float*)d_in[1];
    if (n_in >= 2 && in_sizes[0] == 72) {      // defensive input-order check
        const float* t = drive; drive = Kl; Kl = t;
    }
    float* out = (float*)d_out;
    (void)out_size;

    const size_t shmem = 2 * NBUF * sizeof(float);   // 71808 bytes
    cudaFuncSetAttribute(cml_cluster_kernel,
                         cudaFuncAttributeMaxDynamicSharedMemorySize, (int)shmem);
    cml_cluster_kernel<<<1024, 512, shmem>>>(drive, Kl, out);
}